// round 14
// baseline (speedup 1.0000x reference)
#include <cuda_runtime.h>
#include <cuda_fp16.h>
#include <cstdint>

#define MDIM   1024
#define NHEADS 16
#define HDIM   64
#define BATCH  4
#define SEQ    2048
#define MROWS  (BATCH * SEQ)   // 8192

// Q pre-scale 1/sqrt(64) folded into projection epilogue
#define QSCALE 0.125f

__device__ __align__(16) __half g_qh[BATCH * NHEADS * SEQ * HDIM];  // [B,H,S,dh] fp16
__device__ __align__(16) __half g_kh[BATCH * NHEADS * SEQ * HDIM];
__device__ __align__(16) __half g_vh[BATCH * NHEADS * SEQ * HDIM];
__device__ __align__(16) float  g_ctx[BATCH * SEQ * MDIM];          // [B,S,H*dh] fp32

// ---------------- helpers ----------------------------------------------------
__device__ __forceinline__ void mma16816(float* d, const uint32_t* a,
                                         const uint32_t* b) {
    asm volatile(
        "mma.sync.aligned.m16n8k16.row.col.f32.f16.f16.f32 "
        "{%0,%1,%2,%3}, {%4,%5,%6,%7}, {%8,%9}, {%0,%1,%2,%3};"
        : "+f"(d[0]), "+f"(d[1]), "+f"(d[2]), "+f"(d[3])
        : "r"(a[0]), "r"(a[1]), "r"(a[2]), "r"(a[3]),
          "r"(b[0]), "r"(b[1]));
}
__device__ __forceinline__ uint32_t f2h2(float x, float y) {
    __half2 h = __floats2half2_rn(x, y);
    return *(uint32_t*)&h;
}
__device__ __forceinline__ uint32_t smem_u32(const void* p) {
    uint32_t a;
    asm("{ .reg .u64 t; cvta.to.shared.u64 t, %1; cvt.u32.u64 %0, t; }"
        : "=r"(a) : "l"(p));
    return a;
}
__device__ __forceinline__ void ldmx4(uint32_t* r, uint32_t addr) {
    asm volatile("ldmatrix.sync.aligned.m8n8.x4.shared.b16 {%0,%1,%2,%3}, [%4];"
                 : "=r"(r[0]), "=r"(r[1]), "=r"(r[2]), "=r"(r[3]) : "r"(addr));
}
__device__ __forceinline__ void ldmx4t(uint32_t* r, uint32_t addr) {
    asm volatile("ldmatrix.sync.aligned.m8n8.x4.trans.shared.b16 {%0,%1,%2,%3}, [%4];"
                 : "=r"(r[0]), "=r"(r[1]), "=r"(r[2]), "=r"(r[3]) : "r"(addr));
}
#define CP_ASYNC16(dst, src) \
    asm volatile("cp.async.ca.shared.global [%0], [%1], 16;" \
                 :: "r"(dst), "l"(src) : "memory")
#define CP_COMMIT  asm volatile("cp.async.commit_group;" ::: "memory")
#define CP_WAIT0   asm volatile("cp.async.wait_group 0;" ::: "memory")
#define CP_WAIT1   asm volatile("cp.async.wait_group 1;" ::: "memory")

// ---------------- fp16 tensor-core GEMM (round-13 exact, verified best) -------
#define LDS_H 40

template<bool HEAD_OUT>
__global__ __launch_bounds__(256)
void gemm_mma(const float* __restrict__ A,
              const float* __restrict__ W,
              float* __restrict__ Cf,
              __half* __restrict__ Ch,
              float scale) {
    __shared__ __align__(16) __half As[2][128][LDS_H];
    __shared__ __align__(16) __half Ws[2][128][LDS_H];

    const int tid  = threadIdx.x;
    const int wid  = tid >> 5;
    const int lane = tid & 31;
    const int gid  = lane >> 2;
    const int tid4 = lane & 3;
    const int g    = lane >> 3;
    const int rl   = lane & 7;
    const int wm   = (wid >> 2) * 64;
    const int wn   = (wid & 3) * 32;
    const int bm   = blockIdx.y * 128;
    const int bn   = blockIdx.x * 128;

    const int lrow = tid >> 3;
    const int c4   = tid & 7;
    const float* gA = A + (size_t)(bm + lrow) * MDIM + c4 * 4;
    const float* gW = W + (size_t)(bn + lrow) * MDIM + c4 * 4;

    const uint32_t a_lo = (uint32_t)(((g & 1) * 8 + rl) * (LDS_H * 2) + (g >> 1) * 16);
    const uint32_t w_lo = (uint32_t)(((g >> 1) * 8 + rl) * (LDS_H * 2) + (g & 1) * 16);
    const uint32_t abase[2] = {
        smem_u32(&As[0][0][0]) + a_lo + (uint32_t)wm * (LDS_H * 2),
        smem_u32(&As[1][0][0]) + a_lo + (uint32_t)wm * (LDS_H * 2) };
    const uint32_t wbase[2] = {
        smem_u32(&Ws[0][0][0]) + w_lo + (uint32_t)wn * (LDS_H * 2),
        smem_u32(&Ws[1][0][0]) + w_lo + (uint32_t)wn * (LDS_H * 2) };

    float4 ra[4], rw[4];

    #define LDG_STAGE(kt) do {                                                 \
        const int _k0 = (kt) * 32;                                             \
        _Pragma("unroll")                                                      \
        for (int j = 0; j < 4; j++) {                                          \
            ra[j] = *(const float4*)(gA + (size_t)(j * 32) * MDIM + _k0);      \
            rw[j] = *(const float4*)(gW + (size_t)(j * 32) * MDIM + _k0);      \
        }                                                                      \
    } while (0)

    #define STS_STAGE(s) do {                                                  \
        _Pragma("unroll")                                                      \
        for (int j = 0; j < 4; j++) {                                          \
            uint2 av = { f2h2(ra[j].x, ra[j].y), f2h2(ra[j].z, ra[j].w) };     \
            uint2 wv = { f2h2(rw[j].x, rw[j].y), f2h2(rw[j].z, rw[j].w) };     \
            *(uint2*)&As[s][lrow + j * 32][c4 * 4] = av;                       \
            *(uint2*)&Ws[s][lrow + j * 32][c4 * 4] = wv;                       \
        }                                                                      \
    } while (0)

    float acc[4][4][4] = {};

    LDG_STAGE(0);
    STS_STAGE(0);
    __syncthreads();

    for (int kt = 0; kt < 32; kt++) {
        const int cur = kt & 1;
        if (kt + 1 < 32) LDG_STAGE(kt + 1);

        #pragma unroll
        for (int ks = 0; ks < 2; ks++) {
            uint32_t af[4][4], bf[8];
            #pragma unroll
            for (int i = 0; i < 4; i++)
                ldmx4(af[i], abase[cur] + (uint32_t)(i * 16 * (LDS_H * 2) + ks * 32));
            ldmx4(bf,     wbase[cur] + (uint32_t)(ks * 32));
            ldmx4(bf + 4, wbase[cur] + (uint32_t)(16 * (LDS_H * 2) + ks * 32));
            #pragma unroll
            for (int i = 0; i < 4; i++)
                #pragma unroll
                for (int j = 0; j < 4; j++)
                    mma16816(acc[i][j], af[i], bf + j * 2);
        }

        if (kt + 1 < 32) STS_STAGE(cur ^ 1);
        __syncthreads();
    }

    #pragma unroll
    for (int i = 0; i < 4; i++) {
        #pragma unroll
        for (int j = 0; j < 4; j++) {
            const int n = bn + wn + j * 8 + 2 * tid4;
            #pragma unroll
            for (int half_ = 0; half_ < 2; half_++) {
                const int m = bm + wm + i * 16 + gid + half_ * 8;
                float vx = acc[i][j][half_ * 2];
                float vy = acc[i][j][half_ * 2 + 1];
                if (HEAD_OUT) {
                    const int bb = m >> 11, ss = m & 2047;
                    const int hh = n >> 6,  dd = n & 63;
                    uint32_t hv = f2h2(vx * scale, vy * scale);
                    *(uint32_t*)&Ch[(((size_t)(bb * NHEADS + hh) * SEQ) + ss) * HDIM + dd] = hv;
                } else {
                    float2 v = { vx, vy };
                    *(float2*)&Cf[(size_t)m * MDIM + n] = v;
                }
            }
        }
    }
}

// ---------------- flash attention: softmax/PV interleaved per A-tile ----------
#define FH 72

__global__ __launch_bounds__(128)
void flash_mma(const __half* __restrict__ qh,
               const __half* __restrict__ kh,
               const __half* __restrict__ vh,
               float* __restrict__ ctx) {
    __shared__ __align__(16) __half Ks[2][64][FH];
    __shared__ __align__(16) __half Vs[2][64][FH];

    const int tid  = threadIdx.x;
    const int wid  = tid >> 5;
    const int lane = tid & 31;
    const int gid  = lane >> 2;
    const int tid4 = lane & 3;

    const int bh = blockIdx.y;
    const int b  = bh >> 4;
    const int h  = bh & 15;
    const int q0 = blockIdx.x * 128;

    const __half* qb = qh + (size_t)bh * SEQ * HDIM;
    const __half* kb = kh + (size_t)bh * SEQ * HDIM;
    const __half* vb = vh + (size_t)bh * SEQ * HDIM;

    const int key   = tid & 63;
    const int dbase = (tid >> 6) * 32;
    const uint32_t ksm[2] = { smem_u32(&Ks[0][key][dbase]), smem_u32(&Ks[1][key][dbase]) };
    const uint32_t vsm[2] = { smem_u32(&Vs[0][key][dbase]), smem_u32(&Vs[1][key][dbase]) };

    #define CPKV(t, s) do {                                                     \
        const __half* _ks = kb + ((size_t)(t) * 64 + key) * HDIM + dbase;       \
        const __half* _vs = vb + ((size_t)(t) * 64 + key) * HDIM + dbase;       \
        _Pragma("unroll")                                                       \
        for (int i = 0; i < 4; i++) {                                           \
            CP_ASYNC16(ksm[s] + 16 * i, _ks + 8 * i);                           \
            CP_ASYNC16(vsm[s] + 16 * i, _vs + 8 * i);                           \
        }                                                                       \
    } while (0)

    const int g  = lane >> 3;
    const int rl = lane & 7;
    const uint32_t koff = (uint32_t)(((g >> 1) * 8 + rl) * FH + 8 * (g & 1)) * 2u;
    const uint32_t voff = (uint32_t)((8 * (g & 1) + rl) * FH + 8 * (g >> 1)) * 2u;
    const uint32_t kbase[2] = { smem_u32(&Ks[0][0][0]) + koff, smem_u32(&Ks[1][0][0]) + koff };
    const uint32_t vbase[2] = { smem_u32(&Vs[0][0][0]) + voff, smem_u32(&Vs[1][0][0]) + voff };

    uint32_t aq[2][4][4];
    {
        const __half* qrow = qb + (size_t)q0 * HDIM;
        #pragma unroll
        for (int ia = 0; ia < 2; ia++) {
            const int r = wid * 32 + ia * 16 + gid;
            #pragma unroll
            for (int ks = 0; ks < 4; ks++) {
                const int kc = 16 * ks + 2 * tid4;
                aq[ia][ks][0] = *(const uint32_t*)(qrow + (size_t)r * HDIM + kc);
                aq[ia][ks][1] = *(const uint32_t*)(qrow + (size_t)(r + 8) * HDIM + kc);
                aq[ia][ks][2] = *(const uint32_t*)(qrow + (size_t)r * HDIM + kc + 8);
                aq[ia][ks][3] = *(const uint32_t*)(qrow + (size_t)(r + 8) * HDIM + kc + 8);
            }
        }
    }

    float m[2][2], l[2][2];
    #pragma unroll
    for (int ia = 0; ia < 2; ia++) {
        m[ia][0] = -1e30f; m[ia][1] = -1e30f;
        l[ia][0] = 0.f;    l[ia][1] = 0.f;
    }
    float oacc[2][8][4] = {};

    CPKV(0, 0); CP_COMMIT;
    CPKV(1, 1); CP_COMMIT;
    CP_WAIT1;
    __syncthreads();

    for (int t = 0; t < 32; t++) {
        const int s = t & 1;

        // ---- S = Q K^T : K fragments shared across both A-tiles ----
        float sacc[2][8][4] = {};
        #pragma unroll
        for (int ks = 0; ks < 4; ks++) {
            #pragma unroll
            for (int jp = 0; jp < 4; jp++) {
                uint32_t bf[4];
                ldmx4(bf, kbase[s] + (uint32_t)(2 * jp * 8 * FH + 16 * ks) * 2u);
                mma16816(sacc[0][2 * jp],     aq[0][ks], bf);
                mma16816(sacc[1][2 * jp],     aq[1][ks], bf);
                mma16816(sacc[0][2 * jp + 1], aq[0][ks], bf + 2);
                mma16816(sacc[1][2 * jp + 1], aq[1][ks], bf + 2);
            }
        }

        // ---- per A-tile: softmax then immediately its PV mma ----
        // PV(0) HMMA overlaps softmax(1) MUFU/FMA stalls (independent regs).
        #pragma unroll
        for (int ia = 0; ia < 2; ia++) {
            float mx0 = -1e30f, mx1 = -1e30f;
            #pragma unroll
            for (int j = 0; j < 8; j++) {
                mx0 = fmaxf(mx0, fmaxf(sacc[ia][j][0], sacc[ia][j][1]));
                mx1 = fmaxf(mx1, fmaxf(sacc[ia][j][2], sacc[ia][j][3]));
            }
            #pragma unroll
            for (int off = 1; off <= 2; off <<= 1) {
                mx0 = fmaxf(mx0, __shfl_xor_sync(0xffffffffu, mx0, off));
                mx1 = fmaxf(mx1, __shfl_xor_sync(0xffffffffu, mx1, off));
            }
            const float mn0 = fmaxf(m[ia][0], mx0);
            const float mn1 = fmaxf(m[ia][1], mx1);
            const float sc0 = __expf(m[ia][0] - mn0);
            const float sc1 = __expf(m[ia][1] - mn1);

            float rs0 = 0.f, rs1 = 0.f;
            #pragma unroll
            for (int j = 0; j < 8; j++) {
                sacc[ia][j][0] = __expf(sacc[ia][j][0] - mn0);
                sacc[ia][j][1] = __expf(sacc[ia][j][1] - mn0);
                sacc[ia][j][2] = __expf(sacc[ia][j][2] - mn1);
                sacc[ia][j][3] = __expf(sacc[ia][j][3] - mn1);
                rs0 += sacc[ia][j][0] + sacc[ia][j][1];
                rs1 += sacc[ia][j][2] + sacc[ia][j][3];
            }
            #pragma unroll
            for (int off = 1; off <= 2; off <<= 1) {
                rs0 += __shfl_xor_sync(0xffffffffu, rs0, off);
                rs1 += __shfl_xor_sync(0xffffffffu, rs1, off);
            }
            l[ia][0] = l[ia][0] * sc0 + rs0;  m[ia][0] = mn0;
            l[ia][1] = l[ia][1] * sc1 + rs1;  m[ia][1] = mn1;

            #pragma unroll
            for (int j = 0; j < 8; j++) {
                oacc[ia][j][0] *= sc0;  oacc[ia][j][1] *= sc0;
                oacc[ia][j][2] *= sc1;  oacc[ia][j][3] *= sc1;
            }

            uint32_t ap[4][4];
            #pragma unroll
            for (int ks = 0; ks < 4; ks++) {
                ap[ks][0] = f2h2(sacc[ia][2 * ks][0],     sacc[ia][2 * ks][1]);
                ap[ks][1] = f2h2(sacc[ia][2 * ks][2],     sacc[ia][2 * ks][3]);
                ap[ks][2] = f2h2(sacc[ia][2 * ks + 1][0], sacc[ia][2 * ks + 1][1]);
                ap[ks][3] = f2h2(sacc[ia][2 * ks + 1][2], sacc[ia][2 * ks + 1][3]);
            }

            // PV for this A-tile only
            #pragma unroll
            for (int ks = 0; ks < 4; ks++) {
                #pragma unroll
                for (int jp = 0; jp < 4; jp++) {
                    uint32_t bf[4];
                    ldmx4t(bf, vbase[s] + (uint32_t)(16 * ks * FH + 2 * jp * 8) * 2u);
                    mma16816(oacc[ia][2 * jp],     ap[ks], bf);
                    mma16816(oacc[ia][2 * jp + 1], ap[ks], bf + 2);
                }
            }
        }

        CP_WAIT0;
        __syncthreads();
        if (t + 2 < 32) {
            CPKV(t + 2, s); CP_COMMIT;
        }
    }

    #pragma unroll
    for (int ia = 0; ia < 2; ia++) {
        const int r = q0 + wid * 32 + ia * 16 + gid;
        const float inv0 = 1.f / l[ia][0];
        const float inv1 = 1.f / l[ia][1];
        #pragma unroll
        for (int j = 0; j < 8; j++) {
            const int d = h * HDIM + 8 * j + 2 * tid4;
            float2 v0 = { oacc[ia][j][0] * inv0, oacc[ia][j][1] * inv0 };
            float2 v1 = { oacc[ia][j][2] * inv1, oacc[ia][j][3] * inv1 };
            *(float2*)&ctx[((size_t)(b * SEQ + r))     * MDIM + d] = v0;
            *(float2*)&ctx[((size_t)(b * SEQ + r + 8)) * MDIM + d] = v1;
        }
    }
}

// ---------------- launch -------------------------------------------------------
extern "C" void kernel_launch(void* const* d_in, const int* in_sizes, int n_in,
                              void* d_out, int out_size) {
    const float* q  = (const float*)d_in[0];
    const float* k  = (const float*)d_in[1];
    const float* v  = (const float*)d_in[2];
    const float* wq = (const float*)d_in[3];
    const float* wk = (const float*)d_in[4];
    const float* wv = (const float*)d_in[5];
    const float* wo = (const float*)d_in[6];
    float* out = (float*)d_out;

    __half *qh, *kh, *vh;
    float *ctx;
    cudaGetSymbolAddress((void**)&qh,  g_qh);
    cudaGetSymbolAddress((void**)&kh,  g_kh);
    cudaGetSymbolAddress((void**)&vh,  g_vh);
    cudaGetSymbolAddress((void**)&ctx, g_ctx);

    dim3 gridP(MDIM / 128, MROWS / 128);   // (8, 64)
    gemm_mma<true ><<<gridP, 256>>>(q, wq, nullptr, qh, QSCALE);
    gemm_mma<true ><<<gridP, 256>>>(k, wk, nullptr, kh, 1.0f);
    gemm_mma<true ><<<gridP, 256>>>(v, wv, nullptr, vh, 1.0f);

    dim3 gridF(SEQ / 128, BATCH * NHEADS); // (16, 64)
    flash_mma<<<gridF, 128>>>(qh, kh, vh, ctx);

    gemm_mma<false><<<gridP, 256>>>(ctx, wo, out, nullptr, 1.0f);
}

// round 15
// speedup vs baseline: 1.0378x; 1.0378x over previous
#include <cuda_runtime.h>
#include <cuda_fp16.h>
#include <cstdint>

#define MDIM   1024
#define NHEADS 16
#define HDIM   64
#define BATCH  4
#define SEQ    2048
#define MROWS  (BATCH * SEQ)   // 8192

#define QSCALE 0.125f

__device__ __align__(16) __half g_qh[BATCH * NHEADS * SEQ * HDIM];
__device__ __align__(16) __half g_kh[BATCH * NHEADS * SEQ * HDIM];
__device__ __align__(16) __half g_vh[BATCH * NHEADS * SEQ * HDIM];
__device__ __align__(16) float  g_ctx[BATCH * SEQ * MDIM];

// ---------------- helpers ----------------------------------------------------
__device__ __forceinline__ void mma16816(float* d, const uint32_t* a,
                                         const uint32_t* b) {
    asm volatile(
        "mma.sync.aligned.m16n8k16.row.col.f32.f16.f16.f32 "
        "{%0,%1,%2,%3}, {%4,%5,%6,%7}, {%8,%9}, {%0,%1,%2,%3};"
        : "+f"(d[0]), "+f"(d[1]), "+f"(d[2]), "+f"(d[3])
        : "r"(a[0]), "r"(a[1]), "r"(a[2]), "r"(a[3]),
          "r"(b[0]), "r"(b[1]));
}
__device__ __forceinline__ uint32_t f2h2(float x, float y) {
    __half2 h = __floats2half2_rn(x, y);
    return *(uint32_t*)&h;
}
__device__ __forceinline__ uint32_t smem_u32(const void* p) {
    uint32_t a;
    asm("{ .reg .u64 t; cvta.to.shared.u64 t, %1; cvt.u32.u64 %0, t; }"
        : "=r"(a) : "l"(p));
    return a;
}
__device__ __forceinline__ void ldmx4(uint32_t* r, uint32_t addr) {
    asm volatile("ldmatrix.sync.aligned.m8n8.x4.shared.b16 {%0,%1,%2,%3}, [%4];"
                 : "=r"(r[0]), "=r"(r[1]), "=r"(r[2]), "=r"(r[3]) : "r"(addr));
}
__device__ __forceinline__ void ldmx4t(uint32_t* r, uint32_t addr) {
    asm volatile("ldmatrix.sync.aligned.m8n8.x4.trans.shared.b16 {%0,%1,%2,%3}, [%4];"
                 : "=r"(r[0]), "=r"(r[1]), "=r"(r[2]), "=r"(r[3]) : "r"(addr));
}
#define CP_ASYNC16(dst, src) \
    asm volatile("cp.async.ca.shared.global [%0], [%1], 16;" \
                 :: "r"(dst), "l"(src) : "memory")
#define CP_COMMIT  asm volatile("cp.async.commit_group;" ::: "memory")
#define CP_WAIT0   asm volatile("cp.async.wait_group 0;" ::: "memory")
#define CP_WAIT1   asm volatile("cp.async.wait_group 1;" ::: "memory")

// ---------------- GEMM core (round-13 exact inner loop) -----------------------
#define LDS_H 40

struct ProjArgs {
    const float* A[3];
    const float* W[3];
    __half*      C[3];
    float        scale[3];
};

// Merged q/k/v projection: blockIdx.z selects which (A, W, C, scale).
// Head-layout fp16 output. 1536 CTAs fill launch tails across projections.
__global__ __launch_bounds__(256)
void gemm_proj(ProjArgs args) {
    __shared__ __align__(16) __half As[2][128][LDS_H];
    __shared__ __align__(16) __half Ws[2][128][LDS_H];

    const int z = blockIdx.z;
    const float* A = args.A[z];
    const float* W = args.W[z];
    __half*      C = args.C[z];
    const float  scale = args.scale[z];

    const int tid  = threadIdx.x;
    const int wid  = tid >> 5;
    const int lane = tid & 31;
    const int gid  = lane >> 2;
    const int tid4 = lane & 3;
    const int g    = lane >> 3;
    const int rl   = lane & 7;
    const int wm   = (wid >> 2) * 64;
    const int wn   = (wid & 3) * 32;
    const int bm   = blockIdx.y * 128;
    const int bn   = blockIdx.x * 128;

    const int lrow = tid >> 3;
    const int c4   = tid & 7;
    const float* gA = A + (size_t)(bm + lrow) * MDIM + c4 * 4;
    const float* gW = W + (size_t)(bn + lrow) * MDIM + c4 * 4;

    const uint32_t a_lo = (uint32_t)(((g & 1) * 8 + rl) * (LDS_H * 2) + (g >> 1) * 16);
    const uint32_t w_lo = (uint32_t)(((g >> 1) * 8 + rl) * (LDS_H * 2) + (g & 1) * 16);
    const uint32_t abase[2] = {
        smem_u32(&As[0][0][0]) + a_lo + (uint32_t)wm * (LDS_H * 2),
        smem_u32(&As[1][0][0]) + a_lo + (uint32_t)wm * (LDS_H * 2) };
    const uint32_t wbase[2] = {
        smem_u32(&Ws[0][0][0]) + w_lo + (uint32_t)wn * (LDS_H * 2),
        smem_u32(&Ws[1][0][0]) + w_lo + (uint32_t)wn * (LDS_H * 2) };

    float4 ra[4], rw[4];

    #define LDG_STAGE(kt) do {                                                 \
        const int _k0 = (kt) * 32;                                             \
        _Pragma("unroll")                                                      \
        for (int j = 0; j < 4; j++) {                                          \
            ra[j] = *(const float4*)(gA + (size_t)(j * 32) * MDIM + _k0);      \
            rw[j] = *(const float4*)(gW + (size_t)(j * 32) * MDIM + _k0);      \
        }                                                                      \
    } while (0)

    #define STS_STAGE(s) do {                                                  \
        _Pragma("unroll")                                                      \
        for (int j = 0; j < 4; j++) {                                          \
            uint2 av = { f2h2(ra[j].x, ra[j].y), f2h2(ra[j].z, ra[j].w) };     \
            uint2 wv = { f2h2(rw[j].x, rw[j].y), f2h2(rw[j].z, rw[j].w) };     \
            *(uint2*)&As[s][lrow + j * 32][c4 * 4] = av;                       \
            *(uint2*)&Ws[s][lrow + j * 32][c4 * 4] = wv;                       \
        }                                                                      \
    } while (0)

    float acc[4][4][4] = {};

    LDG_STAGE(0);
    STS_STAGE(0);
    __syncthreads();

    for (int kt = 0; kt < 32; kt++) {
        const int cur = kt & 1;
        if (kt + 1 < 32) LDG_STAGE(kt + 1);

        #pragma unroll
        for (int ks = 0; ks < 2; ks++) {
            uint32_t af[4][4], bf[8];
            #pragma unroll
            for (int i = 0; i < 4; i++)
                ldmx4(af[i], abase[cur] + (uint32_t)(i * 16 * (LDS_H * 2) + ks * 32));
            ldmx4(bf,     wbase[cur] + (uint32_t)(ks * 32));
            ldmx4(bf + 4, wbase[cur] + (uint32_t)(16 * (LDS_H * 2) + ks * 32));
            #pragma unroll
            for (int i = 0; i < 4; i++)
                #pragma unroll
                for (int j = 0; j < 4; j++)
                    mma16816(acc[i][j], af[i], bf + j * 2);
        }

        if (kt + 1 < 32) STS_STAGE(cur ^ 1);
        __syncthreads();
    }

    #pragma unroll
    for (int i = 0; i < 4; i++) {
        #pragma unroll
        for (int j = 0; j < 4; j++) {
            const int n = bn + wn + j * 8 + 2 * tid4;
            #pragma unroll
            for (int half_ = 0; half_ < 2; half_++) {
                const int m = bm + wm + i * 16 + gid + half_ * 8;
                const int bb = m >> 11, ss = m & 2047;
                const int hh = n >> 6,  dd = n & 63;
                uint32_t hv = f2h2(acc[i][j][half_ * 2] * scale,
                                   acc[i][j][half_ * 2 + 1] * scale);
                *(uint32_t*)&C[(((size_t)(bb * NHEADS + hh) * SEQ) + ss) * HDIM + dd] = hv;
            }
        }
    }
}

// Output projection (fp32 out, flat layout) — round-13 exact
__global__ __launch_bounds__(256)
void gemm_out(const float* __restrict__ A,
              const float* __restrict__ W,
              float* __restrict__ Cf) {
    __shared__ __align__(16) __half As[2][128][LDS_H];
    __shared__ __align__(16) __half Ws[2][128][LDS_H];

    const int tid  = threadIdx.x;
    const int wid  = tid >> 5;
    const int lane = tid & 31;
    const int gid  = lane >> 2;
    const int tid4 = lane & 3;
    const int g    = lane >> 3;
    const int rl   = lane & 7;
    const int wm   = (wid >> 2) * 64;
    const int wn   = (wid & 3) * 32;
    const int bm   = blockIdx.y * 128;
    const int bn   = blockIdx.x * 128;

    const int lrow = tid >> 3;
    const int c4   = tid & 7;
    const float* gA = A + (size_t)(bm + lrow) * MDIM + c4 * 4;
    const float* gW = W + (size_t)(bn + lrow) * MDIM + c4 * 4;

    const uint32_t a_lo = (uint32_t)(((g & 1) * 8 + rl) * (LDS_H * 2) + (g >> 1) * 16);
    const uint32_t w_lo = (uint32_t)(((g >> 1) * 8 + rl) * (LDS_H * 2) + (g & 1) * 16);
    const uint32_t abase[2] = {
        smem_u32(&As[0][0][0]) + a_lo + (uint32_t)wm * (LDS_H * 2),
        smem_u32(&As[1][0][0]) + a_lo + (uint32_t)wm * (LDS_H * 2) };
    const uint32_t wbase[2] = {
        smem_u32(&Ws[0][0][0]) + w_lo + (uint32_t)wn * (LDS_H * 2),
        smem_u32(&Ws[1][0][0]) + w_lo + (uint32_t)wn * (LDS_H * 2) };

    float4 ra[4], rw[4];
    float acc[4][4][4] = {};

    LDG_STAGE(0);
    STS_STAGE(0);
    __syncthreads();

    for (int kt = 0; kt < 32; kt++) {
        const int cur = kt & 1;
        if (kt + 1 < 32) LDG_STAGE(kt + 1);

        #pragma unroll
        for (int ks = 0; ks < 2; ks++) {
            uint32_t af[4][4], bf[8];
            #pragma unroll
            for (int i = 0; i < 4; i++)
                ldmx4(af[i], abase[cur] + (uint32_t)(i * 16 * (LDS_H * 2) + ks * 32));
            ldmx4(bf,     wbase[cur] + (uint32_t)(ks * 32));
            ldmx4(bf + 4, wbase[cur] + (uint32_t)(16 * (LDS_H * 2) + ks * 32));
            #pragma unroll
            for (int i = 0; i < 4; i++)
                #pragma unroll
                for (int j = 0; j < 4; j++)
                    mma16816(acc[i][j], af[i], bf + j * 2);
        }

        if (kt + 1 < 32) STS_STAGE(cur ^ 1);
        __syncthreads();
    }

    #pragma unroll
    for (int i = 0; i < 4; i++) {
        #pragma unroll
        for (int j = 0; j < 4; j++) {
            const int n = bn + wn + j * 8 + 2 * tid4;
            #pragma unroll
            for (int half_ = 0; half_ < 2; half_++) {
                const int m = bm + wm + i * 16 + gid + half_ * 8;
                float2 v = { acc[i][j][half_ * 2], acc[i][j][half_ * 2 + 1] };
                *(float2*)&Cf[(size_t)m * MDIM + n] = v;
            }
        }
    }
}

// ---------------- flash attention (round-13 exact) ----------------------------
#define FH 72

__global__ __launch_bounds__(128)
void flash_mma(const __half* __restrict__ qh,
               const __half* __restrict__ kh,
               const __half* __restrict__ vh,
               float* __restrict__ ctx) {
    __shared__ __align__(16) __half Ks[2][64][FH];
    __shared__ __align__(16) __half Vs[2][64][FH];

    const int tid  = threadIdx.x;
    const int wid  = tid >> 5;
    const int lane = tid & 31;
    const int gid  = lane >> 2;
    const int tid4 = lane & 3;

    const int bh = blockIdx.y;
    const int b  = bh >> 4;
    const int h  = bh & 15;
    const int q0 = blockIdx.x * 128;

    const __half* qb = qh + (size_t)bh * SEQ * HDIM;
    const __half* kb = kh + (size_t)bh * SEQ * HDIM;
    const __half* vb = vh + (size_t)bh * SEQ * HDIM;

    const int key   = tid & 63;
    const int dbase = (tid >> 6) * 32;
    const uint32_t ksm[2] = { smem_u32(&Ks[0][key][dbase]), smem_u32(&Ks[1][key][dbase]) };
    const uint32_t vsm[2] = { smem_u32(&Vs[0][key][dbase]), smem_u32(&Vs[1][key][dbase]) };

    #define CPKV(t, s) do {                                                     \
        const __half* _ks = kb + ((size_t)(t) * 64 + key) * HDIM + dbase;       \
        const __half* _vs = vb + ((size_t)(t) * 64 + key) * HDIM + dbase;       \
        _Pragma("unroll")                                                       \
        for (int i = 0; i < 4; i++) {                                           \
            CP_ASYNC16(ksm[s] + 16 * i, _ks + 8 * i);                           \
            CP_ASYNC16(vsm[s] + 16 * i, _vs + 8 * i);                           \
        }                                                                       \
    } while (0)

    const int g  = lane >> 3;
    const int rl = lane & 7;
    const uint32_t koff = (uint32_t)(((g >> 1) * 8 + rl) * FH + 8 * (g & 1)) * 2u;
    const uint32_t voff = (uint32_t)((8 * (g & 1) + rl) * FH + 8 * (g >> 1)) * 2u;
    const uint32_t kbase[2] = { smem_u32(&Ks[0][0][0]) + koff, smem_u32(&Ks[1][0][0]) + koff };
    const uint32_t vbase[2] = { smem_u32(&Vs[0][0][0]) + voff, smem_u32(&Vs[1][0][0]) + voff };

    uint32_t aq[2][4][4];
    {
        const __half* qrow = qb + (size_t)q0 * HDIM;
        #pragma unroll
        for (int ia = 0; ia < 2; ia++) {
            const int r = wid * 32 + ia * 16 + gid;
            #pragma unroll
            for (int ks = 0; ks < 4; ks++) {
                const int kc = 16 * ks + 2 * tid4;
                aq[ia][ks][0] = *(const uint32_t*)(qrow + (size_t)r * HDIM + kc);
                aq[ia][ks][1] = *(const uint32_t*)(qrow + (size_t)(r + 8) * HDIM + kc);
                aq[ia][ks][2] = *(const uint32_t*)(qrow + (size_t)r * HDIM + kc + 8);
                aq[ia][ks][3] = *(const uint32_t*)(qrow + (size_t)(r + 8) * HDIM + kc + 8);
            }
        }
    }

    float m[2][2], l[2][2];
    #pragma unroll
    for (int ia = 0; ia < 2; ia++) {
        m[ia][0] = -1e30f; m[ia][1] = -1e30f;
        l[ia][0] = 0.f;    l[ia][1] = 0.f;
    }
    float oacc[2][8][4] = {};

    CPKV(0, 0); CP_COMMIT;
    CPKV(1, 1); CP_COMMIT;
    CP_WAIT1;
    __syncthreads();

    for (int t = 0; t < 32; t++) {
        const int s = t & 1;

        float sacc[2][8][4] = {};
        #pragma unroll
        for (int ks = 0; ks < 4; ks++) {
            #pragma unroll
            for (int jp = 0; jp < 4; jp++) {
                uint32_t bf[4];
                ldmx4(bf, kbase[s] + (uint32_t)(2 * jp * 8 * FH + 16 * ks) * 2u);
                mma16816(sacc[0][2 * jp],     aq[0][ks], bf);
                mma16816(sacc[1][2 * jp],     aq[1][ks], bf);
                mma16816(sacc[0][2 * jp + 1], aq[0][ks], bf + 2);
                mma16816(sacc[1][2 * jp + 1], aq[1][ks], bf + 2);
            }
        }

        uint32_t ap[2][4][4];
        #pragma unroll
        for (int ia = 0; ia < 2; ia++) {
            float mx0 = -1e30f, mx1 = -1e30f;
            #pragma unroll
            for (int j = 0; j < 8; j++) {
                mx0 = fmaxf(mx0, fmaxf(sacc[ia][j][0], sacc[ia][j][1]));
                mx1 = fmaxf(mx1, fmaxf(sacc[ia][j][2], sacc[ia][j][3]));
            }
            #pragma unroll
            for (int off = 1; off <= 2; off <<= 1) {
                mx0 = fmaxf(mx0, __shfl_xor_sync(0xffffffffu, mx0, off));
                mx1 = fmaxf(mx1, __shfl_xor_sync(0xffffffffu, mx1, off));
            }
            const float mn0 = fmaxf(m[ia][0], mx0);
            const float mn1 = fmaxf(m[ia][1], mx1);
            const float sc0 = __expf(m[ia][0] - mn0);
            const float sc1 = __expf(m[ia][1] - mn1);

            float rs0 = 0.f, rs1 = 0.f;
            #pragma unroll
            for (int j = 0; j < 8; j++) {
                sacc[ia][j][0] = __expf(sacc[ia][j][0] - mn0);
                sacc[ia][j][1] = __expf(sacc[ia][j][1] - mn0);
                sacc[ia][j][2] = __expf(sacc[ia][j][2] - mn1);
                sacc[ia][j][3] = __expf(sacc[ia][j][3] - mn1);
                rs0 += sacc[ia][j][0] + sacc[ia][j][1];
                rs1 += sacc[ia][j][2] + sacc[ia][j][3];
            }
            #pragma unroll
            for (int off = 1; off <= 2; off <<= 1) {
                rs0 += __shfl_xor_sync(0xffffffffu, rs0, off);
                rs1 += __shfl_xor_sync(0xffffffffu, rs1, off);
            }
            l[ia][0] = l[ia][0] * sc0 + rs0;  m[ia][0] = mn0;
            l[ia][1] = l[ia][1] * sc1 + rs1;  m[ia][1] = mn1;

            #pragma unroll
            for (int j = 0; j < 8; j++) {
                oacc[ia][j][0] *= sc0;  oacc[ia][j][1] *= sc0;
                oacc[ia][j][2] *= sc1;  oacc[ia][j][3] *= sc1;
            }
            #pragma unroll
            for (int ks = 0; ks < 4; ks++) {
                ap[ia][ks][0] = f2h2(sacc[ia][2 * ks][0],     sacc[ia][2 * ks][1]);
                ap[ia][ks][1] = f2h2(sacc[ia][2 * ks][2],     sacc[ia][2 * ks][3]);
                ap[ia][ks][2] = f2h2(sacc[ia][2 * ks + 1][0], sacc[ia][2 * ks + 1][1]);
                ap[ia][ks][3] = f2h2(sacc[ia][2 * ks + 1][2], sacc[ia][2 * ks + 1][3]);
            }
        }

        #pragma unroll
        for (int ks = 0; ks < 4; ks++) {
            #pragma unroll
            for (int jp = 0; jp < 4; jp++) {
                uint32_t bf[4];
                ldmx4t(bf, vbase[s] + (uint32_t)(16 * ks * FH + 2 * jp * 8) * 2u);
                mma16816(oacc[0][2 * jp],     ap[0][ks], bf);
                mma16816(oacc[1][2 * jp],     ap[1][ks], bf);
                mma16816(oacc[0][2 * jp + 1], ap[0][ks], bf + 2);
                mma16816(oacc[1][2 * jp + 1], ap[1][ks], bf + 2);
            }
        }

        CP_WAIT0;
        __syncthreads();
        if (t + 2 < 32) {
            CPKV(t + 2, s); CP_COMMIT;
        }
    }

    #pragma unroll
    for (int ia = 0; ia < 2; ia++) {
        const int r = q0 + wid * 32 + ia * 16 + gid;
        const float inv0 = 1.f / l[ia][0];
        const float inv1 = 1.f / l[ia][1];
        #pragma unroll
        for (int j = 0; j < 8; j++) {
            const int d = h * HDIM + 8 * j + 2 * tid4;
            float2 v0 = { oacc[ia][j][0] * inv0, oacc[ia][j][1] * inv0 };
            float2 v1 = { oacc[ia][j][2] * inv1, oacc[ia][j][3] * inv1 };
            *(float2*)&ctx[((size_t)(b * SEQ + r))     * MDIM + d] = v0;
            *(float2*)&ctx[((size_t)(b * SEQ + r + 8)) * MDIM + d] = v1;
        }
    }
}

// ---------------- launch -------------------------------------------------------
extern "C" void kernel_launch(void* const* d_in, const int* in_sizes, int n_in,
                              void* d_out, int out_size) {
    const float* q  = (const float*)d_in[0];
    const float* k  = (const float*)d_in[1];
    const float* v  = (const float*)d_in[2];
    const float* wq = (const float*)d_in[3];
    const float* wk = (const float*)d_in[4];
    const float* wv = (const float*)d_in[5];
    const float* wo = (const float*)d_in[6];
    float* out = (float*)d_out;

    __half *qh, *kh, *vh;
    float *ctx;
    cudaGetSymbolAddress((void**)&qh,  g_qh);
    cudaGetSymbolAddress((void**)&kh,  g_kh);
    cudaGetSymbolAddress((void**)&vh,  g_vh);
    cudaGetSymbolAddress((void**)&ctx, g_ctx);

    ProjArgs pa;
    pa.A[0] = q;  pa.A[1] = k;  pa.A[2] = v;
    pa.W[0] = wq; pa.W[1] = wk; pa.W[2] = wv;
    pa.C[0] = qh; pa.C[1] = kh; pa.C[2] = vh;
    pa.scale[0] = QSCALE; pa.scale[1] = 1.0f; pa.scale[2] = 1.0f;

    dim3 gridP(MDIM / 128, MROWS / 128, 3);   // (8, 64, 3) = 1536 CTAs
    gemm_proj<<<gridP, 256>>>(pa);

    dim3 gridF(SEQ / 128, BATCH * NHEADS);    // (16, 64)
    flash_mma<<<gridF, 128>>>(qh, kh, vh, ctx);

    dim3 gridO(MDIM / 128, MROWS / 128);      // (8, 64)
    gemm_out<<<gridO, 256>>>(ctx, wo, out);
}

// round 16
// speedup vs baseline: 1.0551x; 1.0167x over previous
#include <cuda_runtime.h>
#include <cuda_fp16.h>
#include <cstdint>

#define MDIM   1024
#define NHEADS 16
#define HDIM   64
#define BATCH  4
#define SEQ    2048
#define MROWS  (BATCH * SEQ)   // 8192

#define QSCALE 0.125f

__device__ __align__(16) __half g_w16[4][MDIM * MDIM];   // wq, wk, wv, wo (fp16)
__device__ __align__(16) __half g_qh[BATCH * NHEADS * SEQ * HDIM];
__device__ __align__(16) __half g_kh[BATCH * NHEADS * SEQ * HDIM];
__device__ __align__(16) __half g_vh[BATCH * NHEADS * SEQ * HDIM];
__device__ __align__(16) float  g_ctx[BATCH * SEQ * MDIM];

// ---------------- helpers ----------------------------------------------------
__device__ __forceinline__ void mma16816(float* d, const uint32_t* a,
                                         const uint32_t* b) {
    asm volatile(
        "mma.sync.aligned.m16n8k16.row.col.f32.f16.f16.f32 "
        "{%0,%1,%2,%3}, {%4,%5,%6,%7}, {%8,%9}, {%0,%1,%2,%3};"
        : "+f"(d[0]), "+f"(d[1]), "+f"(d[2]), "+f"(d[3])
        : "r"(a[0]), "r"(a[1]), "r"(a[2]), "r"(a[3]),
          "r"(b[0]), "r"(b[1]));
}
__device__ __forceinline__ uint32_t f2h2(float x, float y) {
    __half2 h = __floats2half2_rn(x, y);
    return *(uint32_t*)&h;
}
__device__ __forceinline__ uint32_t smem_u32(const void* p) {
    uint32_t a;
    asm("{ .reg .u64 t; cvta.to.shared.u64 t, %1; cvt.u32.u64 %0, t; }"
        : "=r"(a) : "l"(p));
    return a;
}
__device__ __forceinline__ void ldmx4(uint32_t* r, uint32_t addr) {
    asm volatile("ldmatrix.sync.aligned.m8n8.x4.shared.b16 {%0,%1,%2,%3}, [%4];"
                 : "=r"(r[0]), "=r"(r[1]), "=r"(r[2]), "=r"(r[3]) : "r"(addr));
}
__device__ __forceinline__ void ldmx4t(uint32_t* r, uint32_t addr) {
    asm volatile("ldmatrix.sync.aligned.m8n8.x4.trans.shared.b16 {%0,%1,%2,%3}, [%4];"
                 : "=r"(r[0]), "=r"(r[1]), "=r"(r[2]), "=r"(r[3]) : "r"(addr));
}
#define CP_ASYNC16(dst, src) \
    asm volatile("cp.async.ca.shared.global [%0], [%1], 16;" \
                 :: "r"(dst), "l"(src) : "memory")
#define CP_COMMIT  asm volatile("cp.async.commit_group;" ::: "memory")
#define CP_WAIT0   asm volatile("cp.async.wait_group 0;" ::: "memory")
#define CP_WAIT1   asm volatile("cp.async.wait_group 1;" ::: "memory")

// ---------------- fp32 -> fp16 convert (weights only, ~5us each) --------------
__global__ __launch_bounds__(256)
void cvt16(const float4* __restrict__ src, uint2* __restrict__ dst, int n4) {
    int i = blockIdx.x * 256 + threadIdx.x;
    if (i < n4) {
        float4 f = src[i];
        uint2 o = { f2h2(f.x, f.y), f2h2(f.z, f.w) };
        dst[i] = o;
    }
}

// ---------------- GEMM geometry ------------------------------------------------
#define LDS_H 40

struct ProjArgs {
    const float*  A[3];
    const __half* W[3];
    __half*       C[3];
    float         scale[3];
};

// Merged q/k/v projection. A: fp32 LDG->cvt->STS (unchanged). W: fp16 cp.async.
__global__ __launch_bounds__(256)
void gemm_proj(ProjArgs args) {
    __shared__ __align__(16) __half As[2][128][LDS_H];
    __shared__ __align__(16) __half Ws[2][128][LDS_H];

    const int z = blockIdx.z;
    const float*  A = args.A[z];
    const __half* W = args.W[z];
    __half*       C = args.C[z];
    const float   scale = args.scale[z];

    const int tid  = threadIdx.x;
    const int wid  = tid >> 5;
    const int lane = tid & 31;
    const int gid  = lane >> 2;
    const int tid4 = lane & 3;
    const int g    = lane >> 3;
    const int rl   = lane & 7;
    const int wm   = (wid >> 2) * 64;
    const int wn   = (wid & 3) * 32;
    const int bm   = blockIdx.y * 128;
    const int bn   = blockIdx.x * 128;

    // A staging (fp32): row = tid>>3, 16B chunk = tid&7
    const int lrow = tid >> 3;
    const int c4   = tid & 7;
    const float* gA = A + (size_t)(bm + lrow) * MDIM + c4 * 4;

    // W cp.async: 2 threads/row, 16 halfs each
    const int wrow  = tid >> 1;
    const int wcol  = (tid & 1) * 16;
    const __half* gW = W + (size_t)(bn + wrow) * MDIM + wcol;
    const uint32_t wsm[2] = {
        smem_u32(&Ws[0][wrow][wcol]), smem_u32(&Ws[1][wrow][wcol]) };

    #define CPW(kt, s) do {                                                    \
        const __half* _w = gW + (kt) * 32;                                     \
        CP_ASYNC16(wsm[s],      _w);                                           \
        CP_ASYNC16(wsm[s] + 16, _w + 8);                                       \
    } while (0)

    const uint32_t a_lo = (uint32_t)(((g & 1) * 8 + rl) * (LDS_H * 2) + (g >> 1) * 16);
    const uint32_t w_lo = (uint32_t)(((g >> 1) * 8 + rl) * (LDS_H * 2) + (g & 1) * 16);
    const uint32_t abase[2] = {
        smem_u32(&As[0][0][0]) + a_lo + (uint32_t)wm * (LDS_H * 2),
        smem_u32(&As[1][0][0]) + a_lo + (uint32_t)wm * (LDS_H * 2) };
    const uint32_t wbase[2] = {
        smem_u32(&Ws[0][0][0]) + w_lo + (uint32_t)wn * (LDS_H * 2),
        smem_u32(&Ws[1][0][0]) + w_lo + (uint32_t)wn * (LDS_H * 2) };

    float4 ra[4];

    #define LDGA_ST(kt) do {                                                   \
        const int _k0 = (kt) * 32;                                             \
        _Pragma("unroll")                                                      \
        for (int j = 0; j < 4; j++)                                            \
            ra[j] = *(const float4*)(gA + (size_t)(j * 32) * MDIM + _k0);      \
    } while (0)

    #define STSA(s) do {                                                       \
        _Pragma("unroll")                                                      \
        for (int j = 0; j < 4; j++) {                                          \
            uint2 av = { f2h2(ra[j].x, ra[j].y), f2h2(ra[j].z, ra[j].w) };     \
            *(uint2*)&As[s][lrow + j * 32][c4 * 4] = av;                       \
        }                                                                      \
    } while (0)

    float acc[4][4][4] = {};

    CPW(0, 0); CP_COMMIT;
    CPW(1, 1); CP_COMMIT;
    LDGA_ST(0);
    STSA(0);
    CP_WAIT1;                // W(0) landed
    __syncthreads();

    for (int kt = 0; kt < 32; kt++) {
        const int cur = kt & 1;
        if (kt + 1 < 32) LDGA_ST(kt + 1);

        #pragma unroll
        for (int ks = 0; ks < 2; ks++) {
            uint32_t af[4][4], bf[8];
            #pragma unroll
            for (int i = 0; i < 4; i++)
                ldmx4(af[i], abase[cur] + (uint32_t)(i * 16 * (LDS_H * 2) + ks * 32));
            ldmx4(bf,     wbase[cur] + (uint32_t)(ks * 32));
            ldmx4(bf + 4, wbase[cur] + (uint32_t)(16 * (LDS_H * 2) + ks * 32));
            #pragma unroll
            for (int i = 0; i < 4; i++)
                #pragma unroll
                for (int j = 0; j < 4; j++)
                    mma16816(acc[i][j], af[i], bf + j * 2);
        }

        if (kt + 1 < 32) {
            STSA(cur ^ 1);
            CP_WAIT0;            // W(kt+1) landed before buffers flip
        }
        __syncthreads();
        if (kt + 2 < 32) { CPW(kt + 2, cur); CP_COMMIT; }
    }

    #pragma unroll
    for (int i = 0; i < 4; i++) {
        #pragma unroll
        for (int j = 0; j < 4; j++) {
            const int n = bn + wn + j * 8 + 2 * tid4;
            #pragma unroll
            for (int half_ = 0; half_ < 2; half_++) {
                const int m = bm + wm + i * 16 + gid + half_ * 8;
                const int bb = m >> 11, ss = m & 2047;
                const int hh = n >> 6,  dd = n & 63;
                uint32_t hv = f2h2(acc[i][j][half_ * 2] * scale,
                                   acc[i][j][half_ * 2 + 1] * scale);
                *(uint32_t*)&C[(((size_t)(bb * NHEADS + hh) * SEQ) + ss) * HDIM + dd] = hv;
            }
        }
    }
}

// Output projection: same structure, fp32 flat output.
__global__ __launch_bounds__(256)
void gemm_out(const float* __restrict__ A,
              const __half* __restrict__ W,
              float* __restrict__ Cf) {
    __shared__ __align__(16) __half As[2][128][LDS_H];
    __shared__ __align__(16) __half Ws[2][128][LDS_H];

    const int tid  = threadIdx.x;
    const int wid  = tid >> 5;
    const int lane = tid & 31;
    const int gid  = lane >> 2;
    const int tid4 = lane & 3;
    const int g    = lane >> 3;
    const int rl   = lane & 7;
    const int wm   = (wid >> 2) * 64;
    const int wn   = (wid & 3) * 32;
    const int bm   = blockIdx.y * 128;
    const int bn   = blockIdx.x * 128;

    const int lrow = tid >> 3;
    const int c4   = tid & 7;
    const float* gA = A + (size_t)(bm + lrow) * MDIM + c4 * 4;

    const int wrow  = tid >> 1;
    const int wcol  = (tid & 1) * 16;
    const __half* gW = W + (size_t)(bn + wrow) * MDIM + wcol;
    const uint32_t wsm[2] = {
        smem_u32(&Ws[0][wrow][wcol]), smem_u32(&Ws[1][wrow][wcol]) };

    const uint32_t a_lo = (uint32_t)(((g & 1) * 8 + rl) * (LDS_H * 2) + (g >> 1) * 16);
    const uint32_t w_lo = (uint32_t)(((g >> 1) * 8 + rl) * (LDS_H * 2) + (g & 1) * 16);
    const uint32_t abase[2] = {
        smem_u32(&As[0][0][0]) + a_lo + (uint32_t)wm * (LDS_H * 2),
        smem_u32(&As[1][0][0]) + a_lo + (uint32_t)wm * (LDS_H * 2) };
    const uint32_t wbase[2] = {
        smem_u32(&Ws[0][0][0]) + w_lo + (uint32_t)wn * (LDS_H * 2),
        smem_u32(&Ws[1][0][0]) + w_lo + (uint32_t)wn * (LDS_H * 2) };

    float4 ra[4];
    float acc[4][4][4] = {};

    CPW(0, 0); CP_COMMIT;
    CPW(1, 1); CP_COMMIT;
    LDGA_ST(0);
    STSA(0);
    CP_WAIT1;
    __syncthreads();

    for (int kt = 0; kt < 32; kt++) {
        const int cur = kt & 1;
        if (kt + 1 < 32) LDGA_ST(kt + 1);

        #pragma unroll
        for (int ks = 0; ks < 2; ks++) {
            uint32_t af[4][4], bf[8];
            #pragma unroll
            for (int i = 0; i < 4; i++)
                ldmx4(af[i], abase[cur] + (uint32_t)(i * 16 * (LDS_H * 2) + ks * 32));
            ldmx4(bf,     wbase[cur] + (uint32_t)(ks * 32));
            ldmx4(bf + 4, wbase[cur] + (uint32_t)(16 * (LDS_H * 2) + ks * 32));
            #pragma unroll
            for (int i = 0; i < 4; i++)
                #pragma unroll
                for (int j = 0; j < 4; j++)
                    mma16816(acc[i][j], af[i], bf + j * 2);
        }

        if (kt + 1 < 32) {
            STSA(cur ^ 1);
            CP_WAIT0;
        }
        __syncthreads();
        if (kt + 2 < 32) { CPW(kt + 2, cur); CP_COMMIT; }
    }

    #pragma unroll
    for (int i = 0; i < 4; i++) {
        #pragma unroll
        for (int j = 0; j < 4; j++) {
            const int n = bn + wn + j * 8 + 2 * tid4;
            #pragma unroll
            for (int half_ = 0; half_ < 2; half_++) {
                const int m = bm + wm + i * 16 + gid + half_ * 8;
                float2 v = { acc[i][j][half_ * 2], acc[i][j][half_ * 2 + 1] };
                *(float2*)&Cf[(size_t)m * MDIM + n] = v;
            }
        }
    }
}

// ---------------- flash attention (round-13/15 exact, verified best) -----------
#define FH 72

__global__ __launch_bounds__(128)
void flash_mma(const __half* __restrict__ qh,
               const __half* __restrict__ kh,
               const __half* __restrict__ vh,
               float* __restrict__ ctx) {
    __shared__ __align__(16) __half Ks[2][64][FH];
    __shared__ __align__(16) __half Vs[2][64][FH];

    const int tid  = threadIdx.x;
    const int wid  = tid >> 5;
    const int lane = tid & 31;
    const int gid  = lane >> 2;
    const int tid4 = lane & 3;

    const int bh = blockIdx.y;
    const int b  = bh >> 4;
    const int h  = bh & 15;
    const int q0 = blockIdx.x * 128;

    const __half* qb = qh + (size_t)bh * SEQ * HDIM;
    const __half* kb = kh + (size_t)bh * SEQ * HDIM;
    const __half* vb = vh + (size_t)bh * SEQ * HDIM;

    const int key   = tid & 63;
    const int dbase = (tid >> 6) * 32;
    const uint32_t ksm[2] = { smem_u32(&Ks[0][key][dbase]), smem_u32(&Ks[1][key][dbase]) };
    const uint32_t vsm[2] = { smem_u32(&Vs[0][key][dbase]), smem_u32(&Vs[1][key][dbase]) };

    #define CPKV(t, s) do {                                                     \
        const __half* _ks = kb + ((size_t)(t) * 64 + key) * HDIM + dbase;       \
        const __half* _vs = vb + ((size_t)(t) * 64 + key) * HDIM + dbase;       \
        _Pragma("unroll")                                                       \
        for (int i = 0; i < 4; i++) {                                           \
            CP_ASYNC16(ksm[s] + 16 * i, _ks + 8 * i);                           \
            CP_ASYNC16(vsm[s] + 16 * i, _vs + 8 * i);                           \
        }                                                                       \
    } while (0)

    const int g  = lane >> 3;
    const int rl = lane & 7;
    const uint32_t koff = (uint32_t)(((g >> 1) * 8 + rl) * FH + 8 * (g & 1)) * 2u;
    const uint32_t voff = (uint32_t)((8 * (g & 1) + rl) * FH + 8 * (g >> 1)) * 2u;
    const uint32_t kbase[2] = { smem_u32(&Ks[0][0][0]) + koff, smem_u32(&Ks[1][0][0]) + koff };
    const uint32_t vbase[2] = { smem_u32(&Vs[0][0][0]) + voff, smem_u32(&Vs[1][0][0]) + voff };

    uint32_t aq[2][4][4];
    {
        const __half* qrow = qb + (size_t)q0 * HDIM;
        #pragma unroll
        for (int ia = 0; ia < 2; ia++) {
            const int r = wid * 32 + ia * 16 + gid;
            #pragma unroll
            for (int ks = 0; ks < 4; ks++) {
                const int kc = 16 * ks + 2 * tid4;
                aq[ia][ks][0] = *(const uint32_t*)(qrow + (size_t)r * HDIM + kc);
                aq[ia][ks][1] = *(const uint32_t*)(qrow + (size_t)(r + 8) * HDIM + kc);
                aq[ia][ks][2] = *(const uint32_t*)(qrow + (size_t)r * HDIM + kc + 8);
                aq[ia][ks][3] = *(const uint32_t*)(qrow + (size_t)(r + 8) * HDIM + kc + 8);
            }
        }
    }

    float m[2][2], l[2][2];
    #pragma unroll
    for (int ia = 0; ia < 2; ia++) {
        m[ia][0] = -1e30f; m[ia][1] = -1e30f;
        l[ia][0] = 0.f;    l[ia][1] = 0.f;
    }
    float oacc[2][8][4] = {};

    CPKV(0, 0); CP_COMMIT;
    CPKV(1, 1); CP_COMMIT;
    CP_WAIT1;
    __syncthreads();

    for (int t = 0; t < 32; t++) {
        const int s = t & 1;

        float sacc[2][8][4] = {};
        #pragma unroll
        for (int ks = 0; ks < 4; ks++) {
            #pragma unroll
            for (int jp = 0; jp < 4; jp++) {
                uint32_t bf[4];
                ldmx4(bf, kbase[s] + (uint32_t)(2 * jp * 8 * FH + 16 * ks) * 2u);
                mma16816(sacc[0][2 * jp],     aq[0][ks], bf);
                mma16816(sacc[1][2 * jp],     aq[1][ks], bf);
                mma16816(sacc[0][2 * jp + 1], aq[0][ks], bf + 2);
                mma16816(sacc[1][2 * jp + 1], aq[1][ks], bf + 2);
            }
        }

        uint32_t ap[2][4][4];
        #pragma unroll
        for (int ia = 0; ia < 2; ia++) {
            float mx0 = -1e30f, mx1 = -1e30f;
            #pragma unroll
            for (int j = 0; j < 8; j++) {
                mx0 = fmaxf(mx0, fmaxf(sacc[ia][j][0], sacc[ia][j][1]));
                mx1 = fmaxf(mx1, fmaxf(sacc[ia][j][2], sacc[ia][j][3]));
            }
            #pragma unroll
            for (int off = 1; off <= 2; off <<= 1) {
                mx0 = fmaxf(mx0, __shfl_xor_sync(0xffffffffu, mx0, off));
                mx1 = fmaxf(mx1, __shfl_xor_sync(0xffffffffu, mx1, off));
            }
            const float mn0 = fmaxf(m[ia][0], mx0);
            const float mn1 = fmaxf(m[ia][1], mx1);
            const float sc0 = __expf(m[ia][0] - mn0);
            const float sc1 = __expf(m[ia][1] - mn1);

            float rs0 = 0.f, rs1 = 0.f;
            #pragma unroll
            for (int j = 0; j < 8; j++) {
                sacc[ia][j][0] = __expf(sacc[ia][j][0] - mn0);
                sacc[ia][j][1] = __expf(sacc[ia][j][1] - mn0);
                sacc[ia][j][2] = __expf(sacc[ia][j][2] - mn1);
                sacc[ia][j][3] = __expf(sacc[ia][j][3] - mn1);
                rs0 += sacc[ia][j][0] + sacc[ia][j][1];
                rs1 += sacc[ia][j][2] + sacc[ia][j][3];
            }
            #pragma unroll
            for (int off = 1; off <= 2; off <<= 1) {
                rs0 += __shfl_xor_sync(0xffffffffu, rs0, off);
                rs1 += __shfl_xor_sync(0xffffffffu, rs1, off);
            }
            l[ia][0] = l[ia][0] * sc0 + rs0;  m[ia][0] = mn0;
            l[ia][1] = l[ia][1] * sc1 + rs1;  m[ia][1] = mn1;

            #pragma unroll
            for (int j = 0; j < 8; j++) {
                oacc[ia][j][0] *= sc0;  oacc[ia][j][1] *= sc0;
                oacc[ia][j][2] *= sc1;  oacc[ia][j][3] *= sc1;
            }
            #pragma unroll
            for (int ks = 0; ks < 4; ks++) {
                ap[ia][ks][0] = f2h2(sacc[ia][2 * ks][0],     sacc[ia][2 * ks][1]);
                ap[ia][ks][1] = f2h2(sacc[ia][2 * ks][2],     sacc[ia][2 * ks][3]);
                ap[ia][ks][2] = f2h2(sacc[ia][2 * ks + 1][0], sacc[ia][2 * ks + 1][1]);
                ap[ia][ks][3] = f2h2(sacc[ia][2 * ks + 1][2], sacc[ia][2 * ks + 1][3]);
            }
        }

        #pragma unroll
        for (int ks = 0; ks < 4; ks++) {
            #pragma unroll
            for (int jp = 0; jp < 4; jp++) {
                uint32_t bf[4];
                ldmx4t(bf, vbase[s] + (uint32_t)(16 * ks * FH + 2 * jp * 8) * 2u);
                mma16816(oacc[0][2 * jp],     ap[0][ks], bf);
                mma16816(oacc[1][2 * jp],     ap[1][ks], bf);
                mma16816(oacc[0][2 * jp + 1], ap[0][ks], bf + 2);
                mma16816(oacc[1][2 * jp + 1], ap[1][ks], bf + 2);
            }
        }

        CP_WAIT0;
        __syncthreads();
        if (t + 2 < 32) {
            CPKV(t + 2, s); CP_COMMIT;
        }
    }

    #pragma unroll
    for (int ia = 0; ia < 2; ia++) {
        const int r = q0 + wid * 32 + ia * 16 + gid;
        const float inv0 = 1.f / l[ia][0];
        const float inv1 = 1.f / l[ia][1];
        #pragma unroll
        for (int j = 0; j < 8; j++) {
            const int d = h * HDIM + 8 * j + 2 * tid4;
            float2 v0 = { oacc[ia][j][0] * inv0, oacc[ia][j][1] * inv0 };
            float2 v1 = { oacc[ia][j][2] * inv1, oacc[ia][j][3] * inv1 };
            *(float2*)&ctx[((size_t)(b * SEQ + r))     * MDIM + d] = v0;
            *(float2*)&ctx[((size_t)(b * SEQ + r + 8)) * MDIM + d] = v1;
        }
    }
}

// ---------------- launch -------------------------------------------------------
extern "C" void kernel_launch(void* const* d_in, const int* in_sizes, int n_in,
                              void* d_out, int out_size) {
    const float* q  = (const float*)d_in[0];
    const float* k  = (const float*)d_in[1];
    const float* v  = (const float*)d_in[2];
    const float* wq = (const float*)d_in[3];
    const float* wk = (const float*)d_in[4];
    const float* wv = (const float*)d_in[5];
    const float* wo = (const float*)d_in[6];
    float* out = (float*)d_out;

    __half (*w16)[MDIM * MDIM];
    __half *qh, *kh, *vh;
    float *ctx;
    cudaGetSymbolAddress((void**)&w16, g_w16);
    cudaGetSymbolAddress((void**)&qh,  g_qh);
    cudaGetSymbolAddress((void**)&kh,  g_kh);
    cudaGetSymbolAddress((void**)&vh,  g_vh);
    cudaGetSymbolAddress((void**)&ctx, g_ctx);

    const int nW = MDIM * MDIM / 4;
    cvt16<<<(nW + 255) / 256, 256>>>((const float4*)wq, (uint2*)w16[0], nW);
    cvt16<<<(nW + 255) / 256, 256>>>((const float4*)wk, (uint2*)w16[1], nW);
    cvt16<<<(nW + 255) / 256, 256>>>((const float4*)wv, (uint2*)w16[2], nW);
    cvt16<<<(nW + 255) / 256, 256>>>((const float4*)wo, (uint2*)w16[3], nW);

    ProjArgs pa;
    pa.A[0] = q;       pa.A[1] = k;       pa.A[2] = v;
    pa.W[0] = w16[0];  pa.W[1] = w16[1];  pa.W[2] = w16[2];
    pa.C[0] = qh;      pa.C[1] = kh;      pa.C[2] = vh;
    pa.scale[0] = QSCALE; pa.scale[1] = 1.0f; pa.scale[2] = 1.0f;

    dim3 gridP(MDIM / 128, MROWS / 128, 3);   // (8, 64, 3)
    gemm_proj<<<gridP, 256>>>(pa);

    dim3 gridF(SEQ / 128, BATCH * NHEADS);    // (16, 64)
    flash_mma<<<gridF, 128>>>(qh, kh, vh, ctx);

    dim3 gridO(MDIM / 128, MROWS / 128);      // (8, 64)
    gemm_out<<<gridO, 256>>>(ctx, w16[3], out);
}